// round 4
// baseline (speedup 1.0000x reference)
#include <cuda_runtime.h>
#include <math.h>

#define BB 64
#define SS 512
#define HH 1024
#define TT 24
#define NROWS (BB*SS)

#define TILE_ROWS 32
#define NTILES (NROWS/TILE_ROWS)       // 1024
#define GRID 148
#define NWARP 8
#define NSTAGE 3
#define NCHUNK (HH/32)                 // 32 chunks of 32 floats (8 float4)
#define STAGE_BYTES (TILE_ROWS*8*16)   // 4096
#define W_BYTES (TT*HH*4)              // 98304
#define SB_OFF   W_BYTES
#define SRED_OFF (W_BYTES+128)
#define FBUF_OFF (W_BYTES+256)
#define SMEM_TOTAL (FBUF_OFF + NWARP*NSTAGE*STAGE_BYTES)   // 196864

// ---------------- device scratch ----------------
__device__ float    g_loss_sum;
__device__ unsigned g_ticket;
__device__ unsigned g_tile;

__device__ __forceinline__ float neg_inf() { return __int_as_float(0xff800000); }

#define FMA2(acc, a, b) \
    asm("fma.rn.f32x2 %0, %1, %2, %0;" : "+l"(acc) : "l"(a), "l"(b))
__device__ __forceinline__ float lo_f(unsigned long long v) { return __uint_as_float((unsigned)v); }
__device__ __forceinline__ float hi_f(unsigned long long v) { return __uint_as_float((unsigned)(v >> 32)); }

__device__ __forceinline__ void cp_async16(unsigned s, const void* g) {
    asm volatile("cp.async.cg.shared.global [%0], [%1], 16;" :: "r"(s), "l"(g));
}
#define CP_COMMIT() asm volatile("cp.async.commit_group;")
#define CP_WAIT1()  asm volatile("cp.async.wait_group 1;")

__device__ __forceinline__ int getmask(const void* p, int mt, long i) {
    return mt == 0 ? (((const unsigned char*)p)[i] != 0)
         : mt == 1 ? (((const float*)p)[i] != 0.0f)
                   : (((const int*)p)[i] != 0);
}

// ================= single fused persistent kernel =================
__global__ void __launch_bounds__(256, 1)
crf_kernel(const float* __restrict__ feats, const float* __restrict__ W,
           const float* __restrict__ bias, const int* __restrict__ target,
           const void* __restrict__ mask_raw, const float* __restrict__ trans,
           float* __restrict__ out, int has_loss) {
    extern __shared__ unsigned char smem[];
    const ulonglong2* sWu = (const ulonglong2*)smem;          // W [24][256] f4
    float* sb   = (float*)(smem + SB_OFF);
    float* sred = (float*)(smem + SRED_OFF);
    __shared__ int   s_flag, s_nz;
    __shared__ float s_tot;

    const int tid  = threadIdx.x;
    const int warp = tid >> 5, lane = tid & 31;
    const float4* f4g = (const float4*)feats;
    float* emis = out + has_loss;

    // ---- stage W once per block (plain LDG -> STS) ----
    {
        float4* sWw = (float4*)smem;
        const float4* Wg = (const float4*)W;
        #pragma unroll 4
        for (int i = tid; i < TT * 256; i += 256) sWw[i] = Wg[i];
        if (tid < TT) sb[tid] = bias[tid];
        if (tid < NWARP) sred[tid] = 0.0f;
        if (tid == 0) { s_flag = 0; s_nz = 0; s_tot = 0.0f; }
    }
    __syncthreads();

    const unsigned fb_base =
        (unsigned)__cvta_generic_to_shared(smem + FBUF_OFF + warp * (NSTAGE * STAGE_BYTES));
    const int rs = lane & 7;
    const int rx = lane * 8;

    const unsigned u0 = *(const unsigned*)mask_raw;
    const int mt = (u0 == 0x01010101u) ? 0 : ((u0 == 0x3F800000u) ? 1 : 2);

    float contrib = 0.0f;

    // ---- per-warp tile-steal loop ----
    for (;;) {
        unsigned tile;
        if (lane == 0) tile = atomicAdd(&g_tile, 1u);
        tile = __shfl_sync(0xffffffffu, tile, 0);
        if (tile >= NTILES) break;
        const long row0 = (long)tile * TILE_ROWS;

        // prologue: stage chunks 0,1
        #pragma unroll
        for (int c = 0; c < 2; c++) {
            unsigned sdst = fb_base + (unsigned)(c % NSTAGE) * STAGE_BYTES;
            #pragma unroll
            for (int j = 0; j < 8; j++) {
                int u = lane + 32 * j;
                int r = u >> 3, kc = u & 7;
                cp_async16(sdst + (unsigned)(r * 8 + (kc ^ (r & 7))) * 16,
                           f4g + ((row0 + r) * 256 + c * 8 + kc));
            }
            CP_COMMIT();
        }

        unsigned long long acc[TT];
        #pragma unroll
        for (int t = 0; t < TT; t++) acc[t] = 0ULL;

        for (int ch = 0; ch < NCHUNK; ch++) {
            CP_WAIT1();
            __syncwarp();
            // prefetch ch+2 (into the stage freed at iteration ch-1)
            const int nc = ch + 2;
            if (nc < NCHUNK) {
                unsigned sdst = fb_base + (unsigned)(nc % NSTAGE) * STAGE_BYTES;
                #pragma unroll
                for (int j = 0; j < 8; j++) {
                    int u = lane + 32 * j;
                    int r = u >> 3, kc = u & 7;
                    cp_async16(sdst + (unsigned)(r * 8 + (kc ^ (r & 7))) * 16,
                               f4g + ((row0 + r) * 256 + nc * 8 + kc));
                }
            }
            CP_COMMIT();

            const ulonglong2* tf = (const ulonglong2*)(smem + FBUF_OFF
                                   + warp * (NSTAGE * STAGE_BYTES)
                                   + (ch % NSTAGE) * STAGE_BYTES);
            const ulonglong2* wc = sWu + ch * 8;
            #pragma unroll 2
            for (int c4 = 0; c4 < 8; c4++) {
                ulonglong2 f = tf[rx + (c4 ^ rs)];
                const ulonglong2* wp = wc + c4;
                #pragma unroll
                for (int t = 0; t < TT; t++) {
                    ulonglong2 w = wp[t * 256];     // uniform address: broadcast LDS
                    FMA2(acc[t], f.x, w.x);
                    FMA2(acc[t], f.y, w.y);
                }
            }
        }

        // ---- in-lane epilogue for this lane's row ----
        const long row = row0 + lane;
        float e[TT];
        float m = neg_inf();
        #pragma unroll
        for (int t = 0; t < TT; t++) {
            e[t] = lo_f(acc[t]) + hi_f(acc[t]) + sb[t];
            emis[row * TT + t] = e[t];
            m = fmaxf(m, e[t]);
        }
        float ex = 0.0f;
        #pragma unroll
        for (int t = 0; t < TT; t++) ex += __expf(e[t] - m);
        const float lse = m + __logf(ex);
        const int tg = target[row];
        float sc = 0.0f;
        #pragma unroll
        for (int t = 0; t < TT; t++) sc = (tg == t) ? e[t] : sc;
        const int s  = (int)(row & (SS - 1));
        const int mk = getmask(mask_raw, mt, row);
        contrib += mk ? (sc - lse) : (s == 0 ? -lse : 0.0f);
    }

    // ---- block reduce fast-path contribution ----
    contrib += __shfl_xor_sync(0xffffffffu, contrib, 16);
    contrib += __shfl_xor_sync(0xffffffffu, contrib, 8);
    contrib += __shfl_xor_sync(0xffffffffu, contrib, 4);
    contrib += __shfl_xor_sync(0xffffffffu, contrib, 2);
    contrib += __shfl_xor_sync(0xffffffffu, contrib, 1);
    if (lane == 0) sred[warp] = contrib;
    __syncthreads();
    if (tid == 0) {
        float part = 0.0f;
        #pragma unroll
        for (int w = 0; w < NWARP; w++) part += sred[w];
        atomicAdd(&g_loss_sum, part);
        __threadfence();
        unsigned tk = atomicAdd(&g_ticket, 1u);
        s_flag = (tk == GRID - 1);
    }
    __syncthreads();
    if (!s_flag) return;

    // ================= last block: finalize =================
    float* st = (float*)(smem + FBUF_OFF);          // transition [576]
    float* sp = st + 576;                            // per-warp scan state [8][24]
    {
        int lnz = 0;
        for (int i = tid; i < TT * TT; i += 256) {
            float v = trans[i];
            st[i] = v;
            lnz |= (v != 0.0f);
        }
        if (lnz) atomicOr(&s_nz, 1);
    }
    __syncthreads();

    if (!s_nz) {
        if (tid == 0) {
            if (has_loss) out[0] = -g_loss_sum / (float)BB;
            g_loss_sum = 0.0f;
            g_ticket = 0u;
            g_tile = 0u;
        }
        return;
    }

    // generic nonzero-transition path (not taken for this dataset)
    {
        float wsum = 0.0f;
        float* msp = sp + warp * TT;
        for (int b = warp; b < BB; b += NWARP) {
            float sum = 0.0f;
            for (int s = lane; s < SS; s += 32) {
                const long idx = (long)b * SS + s;
                if (getmask(mask_raw, mt, idx)) {
                    float v = emis[idx * TT + target[idx]];
                    if (s > 0) v += st[target[idx - 1] * TT + target[idx]];
                    sum += v;
                }
            }
            sum += __shfl_xor_sync(0xffffffffu, sum, 16);
            sum += __shfl_xor_sync(0xffffffffu, sum, 8);
            sum += __shfl_xor_sync(0xffffffffu, sum, 4);
            sum += __shfl_xor_sync(0xffffffffu, sum, 2);
            sum += __shfl_xor_sync(0xffffffffu, sum, 1);

            if (lane < TT) msp[lane] = emis[(long)b * SS * TT + lane];
            __syncwarp();
            for (int s = 1; s < SS; s++) {
                if (getmask(mask_raw, mt, (long)b * SS + s)) {
                    float nv = 0.0f;
                    if (lane < TT) {
                        float mm = neg_inf();
                        #pragma unroll
                        for (int j = 0; j < TT; j++) mm = fmaxf(mm, msp[j] + st[j * TT + lane]);
                        float a = 0.0f;
                        #pragma unroll
                        for (int j = 0; j < TT; j++) a += __expf(msp[j] + st[j * TT + lane] - mm);
                        nv = emis[((long)b * SS + s) * TT + lane] + mm + __logf(a);
                    }
                    __syncwarp();
                    if (lane < TT) msp[lane] = nv;
                    __syncwarp();
                }
            }
            float e2 = (lane < TT) ? msp[lane] : neg_inf();
            float mm = e2;
            mm = fmaxf(mm, __shfl_xor_sync(0xffffffffu, mm, 16));
            mm = fmaxf(mm, __shfl_xor_sync(0xffffffffu, mm, 8));
            mm = fmaxf(mm, __shfl_xor_sync(0xffffffffu, mm, 4));
            mm = fmaxf(mm, __shfl_xor_sync(0xffffffffu, mm, 2));
            mm = fmaxf(mm, __shfl_xor_sync(0xffffffffu, mm, 1));
            float ex2 = (lane < TT) ? __expf(e2 - mm) : 0.0f;
            ex2 += __shfl_xor_sync(0xffffffffu, ex2, 16);
            ex2 += __shfl_xor_sync(0xffffffffu, ex2, 8);
            ex2 += __shfl_xor_sync(0xffffffffu, ex2, 4);
            ex2 += __shfl_xor_sync(0xffffffffu, ex2, 2);
            ex2 += __shfl_xor_sync(0xffffffffu, ex2, 1);
            if (lane == 0) wsum += sum - (mm + __logf(ex2));
        }
        if (lane == 0) atomicAdd(&s_tot, wsum);
    }
    __syncthreads();
    if (tid == 0) {
        if (has_loss) out[0] = -s_tot / (float)BB;
        g_loss_sum = 0.0f;
        g_ticket = 0u;
        g_tile = 0u;
    }
}

// ---------------- launch ----------------
extern "C" void kernel_launch(void* const* d_in, const int* in_sizes, int n_in,
                              void* d_out, int out_size) {
    const float* feats  = (const float*)d_in[0];   // (B,S,H)
    const int*   target = (const int*)d_in[1];     // (B,S)
    const void*  mask   = d_in[2];                 // (B,S) dtype auto-detected
    const float* W      = (const float*)d_in[3];   // (T,H)
    const float* bias   = (const float*)d_in[4];   // (T,)
    const float* trans  = (const float*)d_in[5];   // (T,T)

    float* out = (float*)d_out;
    const int has_loss = (out_size == NROWS * TT + 1) ? 1 : 0;

    static int attr_set = 0;
    if (!attr_set) {
        cudaFuncSetAttribute(crf_kernel, cudaFuncAttributeMaxDynamicSharedMemorySize, SMEM_TOTAL);
        attr_set = 1;
    }

    crf_kernel<<<GRID, 256, SMEM_TOTAL>>>(feats, W, bias, target, mask, trans, out, has_loss);
}